// round 7
// baseline (speedup 1.0000x reference)
#include <cuda_runtime.h>
#include <math.h>
#include <cstdint>

// Problem constants (grid_hw fixed 64x64 for all 8 images)
#define N_TOK   32768
#define EMBED   1024
#define K1      588
#define LLM     2048
#define M2      8192
#define K2      4096

// Scratch (device globals — no allocation allowed)
__device__ float g_pe[(size_t)N_TOK * EMBED];     // gelu(patch GEMM), fp32
__device__ float g_A2[(size_t)M2 * K2];           // tf32 pixels first, then merge-layout A2
__device__ float g_w1[(size_t)EMBED * K1];        // tf32 patch_w
__device__ float g_w2[(size_t)LLM * K2];          // tf32 dense_w

// GEMM tiling: CTA 128x256, 8 warps of 64x64, K-chunk 32
#define BM 128
#define BN 256
#define BK 32
#define SJ 36     // smem row stride in floats (32 + 4 pad): conflict-free frag loads

__device__ __forceinline__ unsigned f2tf32(float x) {
    unsigned r;
    asm("cvt.rna.tf32.f32 %0, %1;" : "=r"(r) : "f"(x));
    return r;
}
__device__ __forceinline__ float gelu_exact(float x) {
    return 0.5f * x * (1.0f + erff(x * 0.70710678118654752f));
}
__device__ __forceinline__ void cp_async16(void* smem_dst, const float* gsrc, int src_bytes) {
    unsigned s = (unsigned)__cvta_generic_to_shared(smem_dst);
    asm volatile("cp.async.cg.shared.global [%0], [%1], 16, %2;\n" :: "r"(s), "l"(gsrc), "r"(src_bytes));
}
__device__ __forceinline__ void cp_commit() { asm volatile("cp.async.commit_group;\n"); }
__device__ __forceinline__ void cp_wait1()  { asm volatile("cp.async.wait_group 1;\n"); }

__device__ __forceinline__ void mma_tf32(float* d, const unsigned* a, const unsigned* b) {
    asm volatile(
        "mma.sync.aligned.m16n8k8.row.col.f32.tf32.tf32.f32 "
        "{%0,%1,%2,%3}, {%4,%5,%6,%7}, {%8,%9}, {%0,%1,%2,%3};"
        : "+f"(d[0]), "+f"(d[1]), "+f"(d[2]), "+f"(d[3])
        : "r"(a[0]), "r"(a[1]), "r"(a[2]), "r"(a[3]), "r"(b[0]), "r"(b[1]));
}

// C[M,N] = A[M,K] * B[N,K]^T + bias (+GELU). A,B tf32-valued fp32 (RNA pre-rounded).
// M%128==0, N%256==0, K%4==0 (K zero-padded to BK in smem).
template<int DO_GELU>
__global__ __launch_bounds__(256, 1) void mma_gemm_nt(
    const float* __restrict__ A, const float* __restrict__ B,
    const float* __restrict__ bias, float* __restrict__ C,
    int M, int N, int K)
{
    extern __shared__ float smem[];
    float* As = smem;                      // [2][BM * SJ]
    float* Bs = smem + 2 * BM * SJ;        // [2][BN * SJ]

    const int tid  = threadIdx.x;
    const int lane = tid & 31;
    const int wid  = tid >> 5;
    const int m_w  = (wid >> 2) * 64;      // warp row offset (0,64)
    const int n_w  = (wid & 3) * 64;       // warp col offset (0,64,128,192)
    const int g    = lane >> 2;            // 0..7
    const int tg   = lane & 3;             // 0..3

    const int m0 = blockIdx.y * BM;
    const int n0 = blockIdx.x * BN;

    float acc[4][8][4];
    #pragma unroll
    for (int i = 0; i < 4; i++)
        #pragma unroll
        for (int j = 0; j < 8; j++)
            #pragma unroll
            for (int r = 0; r < 4; r++) acc[i][j][r] = 0.0f;

    const int nKT = (K + BK - 1) / BK;

    auto issue = [&](int kt, int buf) {
        const int k0 = kt * BK;
        float* Ab = As + buf * BM * SJ;
        float* Bb = Bs + buf * BN * SJ;
        #pragma unroll
        for (int i = 0; i < 4; i++) {          // A: 128 rows * 8 chunks = 1024
            const int idx = tid + i * 256;
            const int r = idx >> 3, c = idx & 7;
            const int kc = k0 + c * 4;
            const int bytes = (kc < K) ? 16 : 0;
            const int ks = (kc < K) ? kc : 0;
            cp_async16(&Ab[r * SJ + c * 4], A + (size_t)(m0 + r) * K + ks, bytes);
        }
        #pragma unroll
        for (int i = 0; i < 8; i++) {          // B: 256 rows * 8 chunks = 2048
            const int idx = tid + i * 256;
            const int r = idx >> 3, c = idx & 7;
            const int kc = k0 + c * 4;
            const int bytes = (kc < K) ? 16 : 0;
            const int ks = (kc < K) ? kc : 0;
            cp_async16(&Bb[r * SJ + c * 4], B + (size_t)(n0 + r) * K + ks, bytes);
        }
    };

    issue(0, 0);
    cp_commit();

    for (int kt = 0; kt < nKT; kt++) {
        if (kt + 1 < nKT) issue(kt + 1, (kt + 1) & 1);
        cp_commit();
        cp_wait1();
        __syncthreads();

        const float* Ab = As + (kt & 1) * BM * SJ;
        const float* Bb = Bs + (kt & 1) * BN * SJ;

        #pragma unroll
        for (int kk = 0; kk < BK; kk += 8) {
            unsigned afr[4][4];
            unsigned bfr[8][2];
            #pragma unroll
            for (int mt = 0; mt < 4; mt++) {
                const int rb = (m_w + mt * 16 + g) * SJ;
                afr[mt][0] = __float_as_uint(Ab[rb + kk + tg]);
                afr[mt][1] = __float_as_uint(Ab[rb + 8 * SJ + kk + tg]);
                afr[mt][2] = __float_as_uint(Ab[rb + kk + 4 + tg]);
                afr[mt][3] = __float_as_uint(Ab[rb + 8 * SJ + kk + 4 + tg]);
            }
            #pragma unroll
            for (int nt = 0; nt < 8; nt++) {
                const int cb = (n_w + nt * 8 + g) * SJ;
                bfr[nt][0] = __float_as_uint(Bb[cb + kk + tg]);
                bfr[nt][1] = __float_as_uint(Bb[cb + kk + 4 + tg]);
            }
            #pragma unroll
            for (int mt = 0; mt < 4; mt++)
                #pragma unroll
                for (int nt = 0; nt < 8; nt++)
                    mma_tf32(acc[mt][nt], afr[mt], bfr[nt]);
        }
        __syncthreads();
    }

    // Epilogue
    #pragma unroll
    for (int mt = 0; mt < 4; mt++) {
        const int r0 = m0 + m_w + mt * 16 + g;
        #pragma unroll
        for (int nt = 0; nt < 8; nt++) {
            const int col = n0 + n_w + nt * 8 + tg * 2;
            const float b0 = bias[col], b1 = bias[col + 1];
            float v0 = acc[mt][nt][0] + b0;
            float v1 = acc[mt][nt][1] + b1;
            float v2 = acc[mt][nt][2] + b0;
            float v3 = acc[mt][nt][3] + b1;
            if (DO_GELU) {
                v0 = gelu_exact(v0); v1 = gelu_exact(v1);
                v2 = gelu_exact(v2); v3 = gelu_exact(v3);
            }
            *reinterpret_cast<float2*>(&C[(size_t)r0 * N + col])       = make_float2(v0, v1);
            *reinterpret_cast<float2*>(&C[(size_t)(r0 + 8) * N + col]) = make_float2(v2, v3);
        }
    }
}

// ---------------- elementwise tf32 RNA rounding ----------------
__global__ __launch_bounds__(256) void cvt_tf32_kernel(
    const float4* __restrict__ in, float4* __restrict__ out, int n4)
{
    int i = blockIdx.x * blockDim.x + threadIdx.x;
    if (i < n4) {
        float4 v = in[i];
        v.x = __uint_as_float(f2tf32(v.x));
        v.y = __uint_as_float(f2tf32(v.y));
        v.z = __uint_as_float(f2tf32(v.z));
        v.w = __uint_as_float(f2tf32(v.w));
        out[i] = v;
    }
}

// ---------------- 2D RoPE + merge transpose, fully coalesced ----------------
// One warp per output row m. Thread handles float4 dim-chunk j of each of the
// 4 source tokens, writes 64 B contiguous at column 16*j.
__global__ __launch_bounds__(256) void rope_merge(
    const float* __restrict__ pe,
    const float* __restrict__ cosx, const float* __restrict__ sinx,
    const float* __restrict__ cosy, const float* __restrict__ siny,
    float* __restrict__ A2)
{
    const int wid  = threadIdx.x >> 5;
    const int lane = threadIdx.x & 31;
    const int m = blockIdx.x * 8 + wid;          // 0..8191
    const int b = m >> 10;
    const int rem = m & 1023;
    const int Y = rem >> 5, X = rem & 31;
    const int y0 = 2 * Y, x0 = 2 * X;

    const float* rows[4];
    #pragma unroll
    for (int p = 0; p < 2; p++)
        #pragma unroll
        for (int q = 0; q < 2; q++)
            rows[p * 2 + q] = pe + ((size_t)(b * 4096 + (y0 + p) * 64 + (x0 + q))) * EMBED;

    float* dst = A2 + (size_t)m * K2;

    #pragma unroll
    for (int it = 0; it < 8; it++) {
        const int j = it * 32 + lane;            // float4 chunk 0..255 (dims 4j..4j+3)
        const bool h1 = (j >= 128);              // second half: y-rope
        const int i0 = h1 ? (2 * j - 256) : (2 * j);
        const float* ct = h1 ? cosy : cosx;
        const float* st = h1 ? siny : sinx;

        float o[4][4];                           // [pq][d]
        #pragma unroll
        for (int p = 0; p < 2; p++) {
            #pragma unroll
            for (int q = 0; q < 2; q++) {
                const int pos = h1 ? (y0 + p) : (x0 + q);
                const float c0 = ct[pos * 256 + i0],     s0 = st[pos * 256 + i0];
                const float c1 = ct[pos * 256 + i0 + 1], s1 = st[pos * 256 + i0 + 1];
                const float4 v = reinterpret_cast<const float4*>(rows[p * 2 + q])[j];
                const int pq = p * 2 + q;
                o[pq][0] = __uint_as_float(f2tf32(v.x * c0 - v.y * s0));
                o[pq][1] = __uint_as_float(f2tf32(v.x * s0 + v.y * c0));
                o[pq][2] = __uint_as_float(f2tf32(v.z * c1 - v.w * s1));
                o[pq][3] = __uint_as_float(f2tf32(v.z * s1 + v.w * c1));
            }
        }
        // dst column e*4 + pq, e = 4j+d  → contiguous 16 floats at 16j
        #pragma unroll
        for (int d = 0; d < 4; d++) {
            float4 w = make_float4(o[0][d], o[1][d], o[2][d], o[3][d]);
            reinterpret_cast<float4*>(dst)[4 * j + d] = w;
        }
    }
}

// ---------------- launch ----------------
extern "C" void kernel_launch(void* const* d_in, const int* in_sizes, int n_in,
                              void* d_out, int out_size)
{
    const float* px = (const float*)d_in[0];   // pixel_values [32768, 588]
    const float* pw = (const float*)d_in[2];   // patch_w [1024, 588]
    const float* pb = (const float*)d_in[3];   // patch_b [1024]
    const float* dw = (const float*)d_in[4];   // dense_w [2048, 4096]
    const float* db = (const float*)d_in[5];   // dense_b [2048]
    const float* cx = (const float*)d_in[6];
    const float* sx = (const float*)d_in[7];
    const float* cy = (const float*)d_in[8];
    const float* sy = (const float*)d_in[9];
    float* out = (float*)d_out;                // [8192, 2048]

    float *pe, *A2, *w1, *w2;
    cudaGetSymbolAddress((void**)&pe, g_pe);
    cudaGetSymbolAddress((void**)&A2, g_A2);
    cudaGetSymbolAddress((void**)&w1, g_w1);
    cudaGetSymbolAddress((void**)&w2, g_w2);

    const int SMEM = 2 * (BM + BN) * SJ * sizeof(float);  // 110592 bytes
    cudaFuncSetAttribute(mma_gemm_nt<1>, cudaFuncAttributeMaxDynamicSharedMemorySize, SMEM);
    cudaFuncSetAttribute(mma_gemm_nt<0>, cudaFuncAttributeMaxDynamicSharedMemorySize, SMEM);

    // Pre-round operands to tf32 (RNA). Pixels staged in g_A2 (overwritten by rope later).
    {
        int n4 = N_TOK * K1 / 4;
        cvt_tf32_kernel<<<(n4 + 255) / 256, 256>>>((const float4*)px, (float4*)A2, n4);
        n4 = EMBED * K1 / 4;
        cvt_tf32_kernel<<<(n4 + 255) / 256, 256>>>((const float4*)pw, (float4*)w1, n4);
        n4 = LLM * K2 / 4;
        cvt_tf32_kernel<<<(n4 + 255) / 256, 256>>>((const float4*)dw, (float4*)w2, n4);
    }

    // Stage 1: pe = gelu(px_tf32 @ pw_tf32^T + pb)
    {
        dim3 grid(EMBED / BN, N_TOK / BM);     // (4, 256)
        mma_gemm_nt<1><<<grid, 256, SMEM>>>(A2, w1, pb, pe, N_TOK, EMBED, K1);
    }

    // Stage 2: RoPE + merge transpose (tf32-rounded) into A2, coalesced
    rope_merge<<<M2 / 8, 256>>>(pe, cx, sx, cy, sy, A2);

    // Stage 3: out = A2 @ dw_tf32^T + db
    {
        dim3 grid(LLM / BN, M2 / BM);          // (8, 64)
        mma_gemm_nt<0><<<grid, 256, SMEM>>>(A2, w2, db, out, M2, LLM, K2);
    }
}

// round 8
// speedup vs baseline: 1.0003x; 1.0003x over previous
#include <cuda_runtime.h>
#include <math.h>
#include <cstdint>

// Problem constants (grid_hw fixed 64x64 for all 8 images)
#define N_TOK   32768
#define EMBED   1024
#define K1      588
#define LLM     2048
#define M2      8192
#define K2      4096

// Scratch (device globals — no allocation allowed)
__device__ float g_pe[(size_t)N_TOK * EMBED];     // gelu(patch GEMM), fp32
__device__ float g_A2[(size_t)M2 * K2];           // tf32 pixels first, then merge-layout A2
__device__ float g_w1[(size_t)EMBED * K1];        // tf32 patch_w
__device__ float g_w2[(size_t)LLM * K2];          // tf32 dense_w

// GEMM tiling: CTA 128x256, 8 warps of 64x64, K-chunk 32
#define BM 128
#define BN 256
#define BK 32
#define SJ 36     // smem row stride in floats (32 + 4 pad): conflict-free frag loads

__device__ __forceinline__ unsigned f2tf32(float x) {
    unsigned r;
    asm("cvt.rna.tf32.f32 %0, %1;" : "=r"(r) : "f"(x));
    return r;
}
__device__ __forceinline__ float gelu_exact(float x) {
    return 0.5f * x * (1.0f + erff(x * 0.70710678118654752f));
}
__device__ __forceinline__ void cp_async16(void* smem_dst, const float* gsrc, int src_bytes) {
    unsigned s = (unsigned)__cvta_generic_to_shared(smem_dst);
    asm volatile("cp.async.cg.shared.global [%0], [%1], 16, %2;\n" :: "r"(s), "l"(gsrc), "r"(src_bytes));
}
__device__ __forceinline__ void cp_commit() { asm volatile("cp.async.commit_group;\n"); }
__device__ __forceinline__ void cp_wait1()  { asm volatile("cp.async.wait_group 1;\n"); }

__device__ __forceinline__ void mma_tf32(float* d, const unsigned* a, const unsigned* b) {
    asm volatile(
        "mma.sync.aligned.m16n8k8.row.col.f32.tf32.tf32.f32 "
        "{%0,%1,%2,%3}, {%4,%5,%6,%7}, {%8,%9}, {%0,%1,%2,%3};"
        : "+f"(d[0]), "+f"(d[1]), "+f"(d[2]), "+f"(d[3])
        : "r"(a[0]), "r"(a[1]), "r"(a[2]), "r"(a[3]), "r"(b[0]), "r"(b[1]));
}

// C[M,N] = A[M,K] * B[N,K]^T + bias (+GELU). A,B tf32-valued fp32 (RNA pre-rounded).
// M%128==0, N%256==0, K%4==0 (K zero-padded to BK in smem).
template<int DO_GELU>
__global__ __launch_bounds__(256, 1) void mma_gemm_nt(
    const float* __restrict__ A, const float* __restrict__ B,
    const float* __restrict__ bias, float* __restrict__ C,
    int M, int N, int K)
{
    extern __shared__ float smem[];
    float* As = smem;                      // [2][BM * SJ]
    float* Bs = smem + 2 * BM * SJ;        // [2][BN * SJ]

    const int tid  = threadIdx.x;
    const int lane = tid & 31;
    const int wid  = tid >> 5;
    const int m_w  = (wid >> 2) * 64;      // warp row offset (0,64)
    const int n_w  = (wid & 3) * 64;       // warp col offset (0,64,128,192)
    const int g    = lane >> 2;            // 0..7
    const int tg   = lane & 3;             // 0..3

    const int m0 = blockIdx.y * BM;
    const int n0 = blockIdx.x * BN;

    float acc[4][8][4];
    #pragma unroll
    for (int i = 0; i < 4; i++)
        #pragma unroll
        for (int j = 0; j < 8; j++)
            #pragma unroll
            for (int r = 0; r < 4; r++) acc[i][j][r] = 0.0f;

    const int nKT = (K + BK - 1) / BK;

    auto issue = [&](int kt, int buf) {
        const int k0 = kt * BK;
        float* Ab = As + buf * BM * SJ;
        float* Bb = Bs + buf * BN * SJ;
        #pragma unroll
        for (int i = 0; i < 4; i++) {          // A: 128 rows * 8 chunks = 1024
            const int idx = tid + i * 256;
            const int r = idx >> 3, c = idx & 7;
            const int kc = k0 + c * 4;
            const int bytes = (kc < K) ? 16 : 0;
            const int ks = (kc < K) ? kc : 0;
            cp_async16(&Ab[r * SJ + c * 4], A + (size_t)(m0 + r) * K + ks, bytes);
        }
        #pragma unroll
        for (int i = 0; i < 8; i++) {          // B: 256 rows * 8 chunks = 2048
            const int idx = tid + i * 256;
            const int r = idx >> 3, c = idx & 7;
            const int kc = k0 + c * 4;
            const int bytes = (kc < K) ? 16 : 0;
            const int ks = (kc < K) ? kc : 0;
            cp_async16(&Bb[r * SJ + c * 4], B + (size_t)(n0 + r) * K + ks, bytes);
        }
    };

    issue(0, 0);
    cp_commit();

    for (int kt = 0; kt < nKT; kt++) {
        if (kt + 1 < nKT) issue(kt + 1, (kt + 1) & 1);
        cp_commit();
        cp_wait1();
        __syncthreads();

        const float* Ab = As + (kt & 1) * BM * SJ;
        const float* Bb = Bs + (kt & 1) * BN * SJ;

        #pragma unroll
        for (int kk = 0; kk < BK; kk += 8) {
            unsigned afr[4][4];
            unsigned bfr[8][2];
            #pragma unroll
            for (int mt = 0; mt < 4; mt++) {
                const int rb = (m_w + mt * 16 + g) * SJ;
                afr[mt][0] = __float_as_uint(Ab[rb + kk + tg]);
                afr[mt][1] = __float_as_uint(Ab[rb + 8 * SJ + kk + tg]);
                afr[mt][2] = __float_as_uint(Ab[rb + kk + 4 + tg]);
                afr[mt][3] = __float_as_uint(Ab[rb + 8 * SJ + kk + 4 + tg]);
            }
            #pragma unroll
            for (int nt = 0; nt < 8; nt++) {
                const int cb = (n_w + nt * 8 + g) * SJ;
                bfr[nt][0] = __float_as_uint(Bb[cb + kk + tg]);
                bfr[nt][1] = __float_as_uint(Bb[cb + kk + 4 + tg]);
            }
            #pragma unroll
            for (int mt = 0; mt < 4; mt++)
                #pragma unroll
                for (int nt = 0; nt < 8; nt++)
                    mma_tf32(acc[mt][nt], afr[mt], bfr[nt]);
        }
        __syncthreads();
    }

    // Epilogue
    #pragma unroll
    for (int mt = 0; mt < 4; mt++) {
        const int r0 = m0 + m_w + mt * 16 + g;
        #pragma unroll
        for (int nt = 0; nt < 8; nt++) {
            const int col = n0 + n_w + nt * 8 + tg * 2;
            const float b0 = bias[col], b1 = bias[col + 1];
            float v0 = acc[mt][nt][0] + b0;
            float v1 = acc[mt][nt][1] + b1;
            float v2 = acc[mt][nt][2] + b0;
            float v3 = acc[mt][nt][3] + b1;
            if (DO_GELU) {
                v0 = gelu_exact(v0); v1 = gelu_exact(v1);
                v2 = gelu_exact(v2); v3 = gelu_exact(v3);
            }
            *reinterpret_cast<float2*>(&C[(size_t)r0 * N + col])       = make_float2(v0, v1);
            *reinterpret_cast<float2*>(&C[(size_t)(r0 + 8) * N + col]) = make_float2(v2, v3);
        }
    }
}

// ---------------- elementwise tf32 RNA rounding ----------------
__global__ __launch_bounds__(256) void cvt_tf32_kernel(
    const float4* __restrict__ in, float4* __restrict__ out, int n4)
{
    int i = blockIdx.x * blockDim.x + threadIdx.x;
    if (i < n4) {
        float4 v = in[i];
        v.x = __uint_as_float(f2tf32(v.x));
        v.y = __uint_as_float(f2tf32(v.y));
        v.z = __uint_as_float(f2tf32(v.z));
        v.w = __uint_as_float(f2tf32(v.w));
        out[i] = v;
    }
}

// ---------------- 2D RoPE + merge transpose, fully coalesced ----------------
// One warp per output row m. Thread handles float4 dim-chunk j of each of the
// 4 source tokens, writes 64 B contiguous at column 16*j.
__global__ __launch_bounds__(256) void rope_merge(
    const float* __restrict__ pe,
    const float* __restrict__ cosx, const float* __restrict__ sinx,
    const float* __restrict__ cosy, const float* __restrict__ siny,
    float* __restrict__ A2)
{
    const int wid  = threadIdx.x >> 5;
    const int lane = threadIdx.x & 31;
    const int m = blockIdx.x * 8 + wid;          // 0..8191
    const int b = m >> 10;
    const int rem = m & 1023;
    const int Y = rem >> 5, X = rem & 31;
    const int y0 = 2 * Y, x0 = 2 * X;

    const float* rows[4];
    #pragma unroll
    for (int p = 0; p < 2; p++)
        #pragma unroll
        for (int q = 0; q < 2; q++)
            rows[p * 2 + q] = pe + ((size_t)(b * 4096 + (y0 + p) * 64 + (x0 + q))) * EMBED;

    float* dst = A2 + (size_t)m * K2;

    #pragma unroll
    for (int it = 0; it < 8; it++) {
        const int j = it * 32 + lane;            // float4 chunk 0..255 (dims 4j..4j+3)
        const bool h1 = (j >= 128);              // second half: y-rope
        const int i0 = h1 ? (2 * j - 256) : (2 * j);
        const float* ct = h1 ? cosy : cosx;
        const float* st = h1 ? siny : sinx;

        float o[4][4];                           // [pq][d]
        #pragma unroll
        for (int p = 0; p < 2; p++) {
            #pragma unroll
            for (int q = 0; q < 2; q++) {
                const int pos = h1 ? (y0 + p) : (x0 + q);
                const float c0 = ct[pos * 256 + i0],     s0 = st[pos * 256 + i0];
                const float c1 = ct[pos * 256 + i0 + 1], s1 = st[pos * 256 + i0 + 1];
                const float4 v = reinterpret_cast<const float4*>(rows[p * 2 + q])[j];
                const int pq = p * 2 + q;
                o[pq][0] = __uint_as_float(f2tf32(v.x * c0 - v.y * s0));
                o[pq][1] = __uint_as_float(f2tf32(v.x * s0 + v.y * c0));
                o[pq][2] = __uint_as_float(f2tf32(v.z * c1 - v.w * s1));
                o[pq][3] = __uint_as_float(f2tf32(v.z * s1 + v.w * c1));
            }
        }
        // dst column e*4 + pq, e = 4j+d  → contiguous 16 floats at 16j
        #pragma unroll
        for (int d = 0; d < 4; d++) {
            float4 w = make_float4(o[0][d], o[1][d], o[2][d], o[3][d]);
            reinterpret_cast<float4*>(dst)[4 * j + d] = w;
        }
    }
}

// ---------------- launch ----------------
extern "C" void kernel_launch(void* const* d_in, const int* in_sizes, int n_in,
                              void* d_out, int out_size)
{
    const float* px = (const float*)d_in[0];   // pixel_values [32768, 588]
    const float* pw = (const float*)d_in[2];   // patch_w [1024, 588]
    const float* pb = (const float*)d_in[3];   // patch_b [1024]
    const float* dw = (const float*)d_in[4];   // dense_w [2048, 4096]
    const float* db = (const float*)d_in[5];   // dense_b [2048]
    const float* cx = (const float*)d_in[6];
    const float* sx = (const float*)d_in[7];
    const float* cy = (const float*)d_in[8];
    const float* sy = (const float*)d_in[9];
    float* out = (float*)d_out;                // [8192, 2048]

    float *pe, *A2, *w1, *w2;
    cudaGetSymbolAddress((void**)&pe, g_pe);
    cudaGetSymbolAddress((void**)&A2, g_A2);
    cudaGetSymbolAddress((void**)&w1, g_w1);
    cudaGetSymbolAddress((void**)&w2, g_w2);

    const int SMEM = 2 * (BM + BN) * SJ * sizeof(float);  // 110592 bytes
    cudaFuncSetAttribute(mma_gemm_nt<1>, cudaFuncAttributeMaxDynamicSharedMemorySize, SMEM);
    cudaFuncSetAttribute(mma_gemm_nt<0>, cudaFuncAttributeMaxDynamicSharedMemorySize, SMEM);

    // Pre-round operands to tf32 (RNA). Pixels staged in g_A2 (overwritten by rope later).
    {
        int n4 = N_TOK * K1 / 4;
        cvt_tf32_kernel<<<(n4 + 255) / 256, 256>>>((const float4*)px, (float4*)A2, n4);
        n4 = EMBED * K1 / 4;
        cvt_tf32_kernel<<<(n4 + 255) / 256, 256>>>((const float4*)pw, (float4*)w1, n4);
        n4 = LLM * K2 / 4;
        cvt_tf32_kernel<<<(n4 + 255) / 256, 256>>>((const float4*)dw, (float4*)w2, n4);
    }

    // Stage 1: pe = gelu(px_tf32 @ pw_tf32^T + pb)
    {
        dim3 grid(EMBED / BN, N_TOK / BM);     // (4, 256)
        mma_gemm_nt<1><<<grid, 256, SMEM>>>(A2, w1, pb, pe, N_TOK, EMBED, K1);
    }

    // Stage 2: RoPE + merge transpose (tf32-rounded) into A2, coalesced
    rope_merge<<<M2 / 8, 256>>>(pe, cx, sx, cy, sy, A2);

    // Stage 3: out = A2 @ dw_tf32^T + db
    {
        dim3 grid(LLM / BN, M2 / BM);          // (8, 64)
        mma_gemm_nt<0><<<grid, 256, SMEM>>>(A2, w2, db, out, M2, LLM, K2);
    }
}

// round 9
// speedup vs baseline: 1.0015x; 1.0012x over previous
#include <cuda_runtime.h>
#include <math.h>
#include <cstdint>

// Problem constants (grid_hw fixed 64x64 for all 8 images)
#define N_TOK   32768
#define EMBED   1024
#define K1      588
#define LLM     2048
#define M2      8192
#define K2      4096

// Scratch (device globals — no allocation allowed)
__device__ float g_pe[(size_t)N_TOK * EMBED];     // gelu(patch GEMM), fp32
__device__ float g_A2[(size_t)M2 * K2];           // tf32 pixels first, then merge-layout A2
__device__ float g_w1[(size_t)EMBED * K1];        // tf32 patch_w
__device__ float g_w2[(size_t)LLM * K2];          // tf32 dense_w

// GEMM tiling: CTA 128x256, 8 warps of 64x64, K-chunk 32
#define BM 128
#define BN 256
#define BK 32
#define SJ 36     // smem row stride in floats (32 + 4 pad): conflict-free frag loads

__device__ __forceinline__ unsigned f2tf32(float x) {
    unsigned r;
    asm("cvt.rna.tf32.f32 %0, %1;" : "=r"(r) : "f"(x));
    return r;
}
__device__ __forceinline__ float gelu_exact(float x) {
    return 0.5f * x * (1.0f + erff(x * 0.70710678118654752f));
}
__device__ __forceinline__ void cp_async16(void* smem_dst, const float* gsrc, int src_bytes) {
    unsigned s = (unsigned)__cvta_generic_to_shared(smem_dst);
    asm volatile("cp.async.cg.shared.global [%0], [%1], 16, %2;\n" :: "r"(s), "l"(gsrc), "r"(src_bytes));
}
__device__ __forceinline__ void cp_commit() { asm volatile("cp.async.commit_group;\n"); }
__device__ __forceinline__ void cp_wait1()  { asm volatile("cp.async.wait_group 1;\n"); }

__device__ __forceinline__ void mma_tf32(float* d, const unsigned* a, const unsigned* b) {
    asm volatile(
        "mma.sync.aligned.m16n8k8.row.col.f32.tf32.tf32.f32 "
        "{%0,%1,%2,%3}, {%4,%5,%6,%7}, {%8,%9}, {%0,%1,%2,%3};"
        : "+f"(d[0]), "+f"(d[1]), "+f"(d[2]), "+f"(d[3])
        : "r"(a[0]), "r"(a[1]), "r"(a[2]), "r"(a[3]), "r"(b[0]), "r"(b[1]));
}

// C[M,N] = A[M,K] * B[N,K]^T + bias (+GELU). A,B tf32-valued fp32 (RNA pre-rounded).
// M%128==0, N%256==0, K%4==0 (K zero-padded to BK in smem).
template<int DO_GELU>
__global__ __launch_bounds__(256, 1) void mma_gemm_nt(
    const float* __restrict__ A, const float* __restrict__ B,
    const float* __restrict__ bias, float* __restrict__ C,
    int M, int N, int K)
{
    extern __shared__ float smem[];
    float* As = smem;                      // [2][BM * SJ]
    float* Bs = smem + 2 * BM * SJ;        // [2][BN * SJ]

    const int tid  = threadIdx.x;
    const int lane = tid & 31;
    const int wid  = tid >> 5;
    const int m_w  = (wid >> 2) * 64;      // warp row offset (0,64)
    const int n_w  = (wid & 3) * 64;       // warp col offset (0,64,128,192)
    const int g    = lane >> 2;            // 0..7
    const int tg   = lane & 3;             // 0..3

    const int m0 = blockIdx.y * BM;
    const int n0 = blockIdx.x * BN;

    float acc[4][8][4];
    #pragma unroll
    for (int i = 0; i < 4; i++)
        #pragma unroll
        for (int j = 0; j < 8; j++)
            #pragma unroll
            for (int r = 0; r < 4; r++) acc[i][j][r] = 0.0f;

    const int nKT = (K + BK - 1) / BK;

    auto issue = [&](int kt, int buf) {
        const int k0 = kt * BK;
        float* Ab = As + buf * BM * SJ;
        float* Bb = Bs + buf * BN * SJ;
        #pragma unroll
        for (int i = 0; i < 4; i++) {          // A: 128 rows * 8 chunks = 1024
            const int idx = tid + i * 256;
            const int r = idx >> 3, c = idx & 7;
            const int kc = k0 + c * 4;
            const int bytes = (kc < K) ? 16 : 0;
            const int ks = (kc < K) ? kc : 0;
            cp_async16(&Ab[r * SJ + c * 4], A + (size_t)(m0 + r) * K + ks, bytes);
        }
        #pragma unroll
        for (int i = 0; i < 8; i++) {          // B: 256 rows * 8 chunks = 2048
            const int idx = tid + i * 256;
            const int r = idx >> 3, c = idx & 7;
            const int kc = k0 + c * 4;
            const int bytes = (kc < K) ? 16 : 0;
            const int ks = (kc < K) ? kc : 0;
            cp_async16(&Bb[r * SJ + c * 4], B + (size_t)(n0 + r) * K + ks, bytes);
        }
    };

    issue(0, 0);
    cp_commit();

    for (int kt = 0; kt < nKT; kt++) {
        if (kt + 1 < nKT) issue(kt + 1, (kt + 1) & 1);
        cp_commit();
        cp_wait1();
        __syncthreads();

        const float* Ab = As + (kt & 1) * BM * SJ;
        const float* Bb = Bs + (kt & 1) * BN * SJ;

        #pragma unroll
        for (int kk = 0; kk < BK; kk += 8) {
            unsigned afr[4][4];
            unsigned bfr[8][2];
            #pragma unroll
            for (int mt = 0; mt < 4; mt++) {
                const int rb = (m_w + mt * 16 + g) * SJ;
                afr[mt][0] = __float_as_uint(Ab[rb + kk + tg]);
                afr[mt][1] = __float_as_uint(Ab[rb + 8 * SJ + kk + tg]);
                afr[mt][2] = __float_as_uint(Ab[rb + kk + 4 + tg]);
                afr[mt][3] = __float_as_uint(Ab[rb + 8 * SJ + kk + 4 + tg]);
            }
            #pragma unroll
            for (int nt = 0; nt < 8; nt++) {
                const int cb = (n_w + nt * 8 + g) * SJ;
                bfr[nt][0] = __float_as_uint(Bb[cb + kk + tg]);
                bfr[nt][1] = __float_as_uint(Bb[cb + kk + 4 + tg]);
            }
            #pragma unroll
            for (int mt = 0; mt < 4; mt++)
                #pragma unroll
                for (int nt = 0; nt < 8; nt++)
                    mma_tf32(acc[mt][nt], afr[mt], bfr[nt]);
        }
        __syncthreads();
    }

    // Epilogue
    #pragma unroll
    for (int mt = 0; mt < 4; mt++) {
        const int r0 = m0 + m_w + mt * 16 + g;
        #pragma unroll
        for (int nt = 0; nt < 8; nt++) {
            const int col = n0 + n_w + nt * 8 + tg * 2;
            const float b0 = bias[col], b1 = bias[col + 1];
            float v0 = acc[mt][nt][0] + b0;
            float v1 = acc[mt][nt][1] + b1;
            float v2 = acc[mt][nt][2] + b0;
            float v3 = acc[mt][nt][3] + b1;
            if (DO_GELU) {
                v0 = gelu_exact(v0); v1 = gelu_exact(v1);
                v2 = gelu_exact(v2); v3 = gelu_exact(v3);
            }
            *reinterpret_cast<float2*>(&C[(size_t)r0 * N + col])       = make_float2(v0, v1);
            *reinterpret_cast<float2*>(&C[(size_t)(r0 + 8) * N + col]) = make_float2(v2, v3);
        }
    }
}

// ---------------- elementwise tf32 RNA rounding ----------------
__global__ __launch_bounds__(256) void cvt_tf32_kernel(
    const float4* __restrict__ in, float4* __restrict__ out, int n4)
{
    int i = blockIdx.x * blockDim.x + threadIdx.x;
    if (i < n4) {
        float4 v = in[i];
        v.x = __uint_as_float(f2tf32(v.x));
        v.y = __uint_as_float(f2tf32(v.y));
        v.z = __uint_as_float(f2tf32(v.z));
        v.w = __uint_as_float(f2tf32(v.w));
        out[i] = v;
    }
}

// ---------------- 2D RoPE + merge transpose, fully coalesced ----------------
// One warp per output row m. Thread handles float4 dim-chunk j of each of the
// 4 source tokens, writes 64 B contiguous at column 16*j.
__global__ __launch_bounds__(256) void rope_merge(
    const float* __restrict__ pe,
    const float* __restrict__ cosx, const float* __restrict__ sinx,
    const float* __restrict__ cosy, const float* __restrict__ siny,
    float* __restrict__ A2)
{
    const int wid  = threadIdx.x >> 5;
    const int lane = threadIdx.x & 31;
    const int m = blockIdx.x * 8 + wid;          // 0..8191
    const int b = m >> 10;
    const int rem = m & 1023;
    const int Y = rem >> 5, X = rem & 31;
    const int y0 = 2 * Y, x0 = 2 * X;

    const float* rows[4];
    #pragma unroll
    for (int p = 0; p < 2; p++)
        #pragma unroll
        for (int q = 0; q < 2; q++)
            rows[p * 2 + q] = pe + ((size_t)(b * 4096 + (y0 + p) * 64 + (x0 + q))) * EMBED;

    float* dst = A2 + (size_t)m * K2;

    #pragma unroll
    for (int it = 0; it < 8; it++) {
        const int j = it * 32 + lane;            // float4 chunk 0..255 (dims 4j..4j+3)
        const bool h1 = (j >= 128);              // second half: y-rope
        const int i0 = h1 ? (2 * j - 256) : (2 * j);
        const float* ct = h1 ? cosy : cosx;
        const float* st = h1 ? siny : sinx;

        float o[4][4];                           // [pq][d]
        #pragma unroll
        for (int p = 0; p < 2; p++) {
            #pragma unroll
            for (int q = 0; q < 2; q++) {
                const int pos = h1 ? (y0 + p) : (x0 + q);
                const float c0 = ct[pos * 256 + i0],     s0 = st[pos * 256 + i0];
                const float c1 = ct[pos * 256 + i0 + 1], s1 = st[pos * 256 + i0 + 1];
                const float4 v = reinterpret_cast<const float4*>(rows[p * 2 + q])[j];
                const int pq = p * 2 + q;
                o[pq][0] = __uint_as_float(f2tf32(v.x * c0 - v.y * s0));
                o[pq][1] = __uint_as_float(f2tf32(v.x * s0 + v.y * c0));
                o[pq][2] = __uint_as_float(f2tf32(v.z * c1 - v.w * s1));
                o[pq][3] = __uint_as_float(f2tf32(v.z * s1 + v.w * c1));
            }
        }
        // dst column e*4 + pq, e = 4j+d  → contiguous 16 floats at 16j
        #pragma unroll
        for (int d = 0; d < 4; d++) {
            float4 w = make_float4(o[0][d], o[1][d], o[2][d], o[3][d]);
            reinterpret_cast<float4*>(dst)[4 * j + d] = w;
        }
    }
}

// ---------------- launch ----------------
extern "C" void kernel_launch(void* const* d_in, const int* in_sizes, int n_in,
                              void* d_out, int out_size)
{
    const float* px = (const float*)d_in[0];   // pixel_values [32768, 588]
    const float* pw = (const float*)d_in[2];   // patch_w [1024, 588]
    const float* pb = (const float*)d_in[3];   // patch_b [1024]
    const float* dw = (const float*)d_in[4];   // dense_w [2048, 4096]
    const float* db = (const float*)d_in[5];   // dense_b [2048]
    const float* cx = (const float*)d_in[6];
    const float* sx = (const float*)d_in[7];
    const float* cy = (const float*)d_in[8];
    const float* sy = (const float*)d_in[9];
    float* out = (float*)d_out;                // [8192, 2048]

    float *pe, *A2, *w1, *w2;
    cudaGetSymbolAddress((void**)&pe, g_pe);
    cudaGetSymbolAddress((void**)&A2, g_A2);
    cudaGetSymbolAddress((void**)&w1, g_w1);
    cudaGetSymbolAddress((void**)&w2, g_w2);

    const int SMEM = 2 * (BM + BN) * SJ * sizeof(float);  // 110592 bytes
    cudaFuncSetAttribute(mma_gemm_nt<1>, cudaFuncAttributeMaxDynamicSharedMemorySize, SMEM);
    cudaFuncSetAttribute(mma_gemm_nt<0>, cudaFuncAttributeMaxDynamicSharedMemorySize, SMEM);

    // Pre-round operands to tf32 (RNA). Pixels staged in g_A2 (overwritten by rope later).
    {
        int n4 = N_TOK * K1 / 4;
        cvt_tf32_kernel<<<(n4 + 255) / 256, 256>>>((const float4*)px, (float4*)A2, n4);
        n4 = EMBED * K1 / 4;
        cvt_tf32_kernel<<<(n4 + 255) / 256, 256>>>((const float4*)pw, (float4*)w1, n4);
        n4 = LLM * K2 / 4;
        cvt_tf32_kernel<<<(n4 + 255) / 256, 256>>>((const float4*)dw, (float4*)w2, n4);
    }

    // Stage 1: pe = gelu(px_tf32 @ pw_tf32^T + pb)
    {
        dim3 grid(EMBED / BN, N_TOK / BM);     // (4, 256)
        mma_gemm_nt<1><<<grid, 256, SMEM>>>(A2, w1, pb, pe, N_TOK, EMBED, K1);
    }

    // Stage 2: RoPE + merge transpose (tf32-rounded) into A2, coalesced
    rope_merge<<<M2 / 8, 256>>>(pe, cx, sx, cy, sy, A2);

    // Stage 3: out = A2 @ dw_tf32^T + db
    {
        dim3 grid(LLM / BN, M2 / BM);          // (8, 64)
        mma_gemm_nt<0><<<grid, 256, SMEM>>>(A2, w2, db, out, M2, LLM, K2);
    }
}

// round 10
// speedup vs baseline: 1.2156x; 1.2138x over previous
#include <cuda_runtime.h>
#include <math.h>
#include <cstdint>

// Problem constants (grid_hw fixed 64x64 for all 8 images)
#define N_TOK   32768
#define EMBED   1024
#define K1      588
#define LLM     2048
#define M2      8192
#define K2      4096

// Scratch (device globals — no allocation allowed)
__device__ float g_pe[(size_t)N_TOK * EMBED];     // gelu(patch GEMM), fp32
__device__ float g_A2[(size_t)M2 * K2];           // tf32 pixels first, then merge-layout A2
__device__ float g_w1[(size_t)EMBED * K1];        // tf32 patch_w
__device__ float g_w2[(size_t)LLM * K2];          // tf32 dense_w

// GEMM tiling: CTA 128x128, 8 warps of 64x32, K-chunk 32, 2 CTAs/SM
#define BM 128
#define BN 128
#define BK 32
#define SJ 36     // smem row stride in floats (32+4): conflict-free ldmatrix & stores

__device__ __forceinline__ unsigned f2tf32(float x) {
    unsigned r;
    asm("cvt.rna.tf32.f32 %0, %1;" : "=r"(r) : "f"(x));
    return r;
}
__device__ __forceinline__ float gelu_exact(float x) {
    return 0.5f * x * (1.0f + erff(x * 0.70710678118654752f));
}
__device__ __forceinline__ void cp_async16(void* smem_dst, const float* gsrc, int src_bytes) {
    unsigned s = (unsigned)__cvta_generic_to_shared(smem_dst);
    asm volatile("cp.async.cg.shared.global [%0], [%1], 16, %2;\n" :: "r"(s), "l"(gsrc), "r"(src_bytes));
}
__device__ __forceinline__ void cp_commit() { asm volatile("cp.async.commit_group;\n"); }
__device__ __forceinline__ void cp_wait1()  { asm volatile("cp.async.wait_group 1;\n"); }

__device__ __forceinline__ void ldmx4(unsigned* r, unsigned saddr) {
    asm volatile("ldmatrix.sync.aligned.m8n8.x4.shared.b16 {%0,%1,%2,%3}, [%4];"
        : "=r"(r[0]), "=r"(r[1]), "=r"(r[2]), "=r"(r[3]) : "r"(saddr));
}

__device__ __forceinline__ void mma_tf32(float* d, const unsigned* a, const unsigned* b) {
    asm volatile(
        "mma.sync.aligned.m16n8k8.row.col.f32.tf32.tf32.f32 "
        "{%0,%1,%2,%3}, {%4,%5,%6,%7}, {%8,%9}, {%0,%1,%2,%3};"
        : "+f"(d[0]), "+f"(d[1]), "+f"(d[2]), "+f"(d[3])
        : "r"(a[0]), "r"(a[1]), "r"(a[2]), "r"(a[3]), "r"(b[0]), "r"(b[1]));
}

// C[M,N] = A[M,K] * B[N,K]^T + bias (+GELU). A,B tf32-valued fp32 (RNA pre-rounded).
// M%128==0, N%128==0, K%4==0 (K zero-padded to BK in smem via cp.async zfill).
template<int DO_GELU>
__global__ __launch_bounds__(256, 2) void mma_gemm_nt(
    const float* __restrict__ A, const float* __restrict__ B,
    const float* __restrict__ bias, float* __restrict__ C,
    int M, int N, int K)
{
    extern __shared__ float smem[];
    float* As = smem;                      // [2][BM * SJ]
    float* Bs = smem + 2 * BM * SJ;        // [2][BN * SJ]

    const int tid  = threadIdx.x;
    const int lane = tid & 31;
    const int wid  = tid >> 5;
    const int m_w  = (wid >> 2) * 64;      // warp row offset (0,64)
    const int n_w  = (wid & 3) * 32;       // warp col offset (0,32,64,96)
    const int g    = lane >> 2;            // 0..7
    const int tg   = lane & 3;             // 0..3

    const int m0 = blockIdx.y * BM;
    const int n0 = blockIdx.x * BN;

    // ldmatrix per-thread fragment address offsets (bytes into a buffer)
    const unsigned sm_u  = (unsigned)__cvta_generic_to_shared(smem);
    const unsigned As_u  = sm_u;
    const unsigned Bs_u  = sm_u + 2u * BM * SJ * 4u;
    const int lr8   = lane & 7;
    const int lsel1 = (lane >> 3) & 1;     // tile-pair selector (rows +8 / k +4)
    const int lsel2 = (lane >> 4) & 1;
    unsigned aoff[4], boff[2];
    #pragma unroll
    for (int mt = 0; mt < 4; mt++)
        aoff[mt] = ((m_w + mt * 16 + lr8 + lsel1 * 8) * SJ + lsel2 * 4) * 4u;
    #pragma unroll
    for (int p = 0; p < 2; p++)
        boff[p] = ((n_w + p * 16 + lr8 + lsel2 * 8) * SJ + lsel1 * 4) * 4u;

    float acc[4][4][4];
    #pragma unroll
    for (int i = 0; i < 4; i++)
        #pragma unroll
        for (int j = 0; j < 4; j++)
            #pragma unroll
            for (int r = 0; r < 4; r++) acc[i][j][r] = 0.0f;

    const int nKT = (K + BK - 1) / BK;

    auto issue = [&](int kt, int buf) {
        const int k0 = kt * BK;
        float* Ab = As + buf * BM * SJ;
        float* Bb = Bs + buf * BN * SJ;
        #pragma unroll
        for (int i = 0; i < 4; i++) {          // A: 128 rows * 8 chunks = 1024
            const int idx = tid + i * 256;
            const int r = idx >> 3, c = idx & 7;
            const int kc = k0 + c * 4;
            const int bytes = (kc < K) ? 16 : 0;
            const int ks = (kc < K) ? kc : 0;
            cp_async16(&Ab[r * SJ + c * 4], A + (size_t)(m0 + r) * K + ks, bytes);
        }
        #pragma unroll
        for (int i = 0; i < 4; i++) {          // B: 128 rows * 8 chunks = 1024
            const int idx = tid + i * 256;
            const int r = idx >> 3, c = idx & 7;
            const int kc = k0 + c * 4;
            const int bytes = (kc < K) ? 16 : 0;
            const int ks = (kc < K) ? kc : 0;
            cp_async16(&Bb[r * SJ + c * 4], B + (size_t)(n0 + r) * K + ks, bytes);
        }
    };

    issue(0, 0);
    cp_commit();

    for (int kt = 0; kt < nKT; kt++) {
        if (kt + 1 < nKT) issue(kt + 1, (kt + 1) & 1);
        cp_commit();
        cp_wait1();
        __syncthreads();

        const unsigned Abase = As_u + (unsigned)(kt & 1) * BM * SJ * 4u;
        const unsigned Bbase = Bs_u + (unsigned)(kt & 1) * BN * SJ * 4u;

        #pragma unroll
        for (int kk = 0; kk < BK; kk += 8) {
            unsigned afr[4][4];
            unsigned bfr[2][4];   // {b0(nt=2p), b1(nt=2p), b0(nt=2p+1), b1(nt=2p+1)}
            #pragma unroll
            for (int mt = 0; mt < 4; mt++)
                ldmx4(afr[mt], Abase + aoff[mt] + kk * 4u);
            #pragma unroll
            for (int p = 0; p < 2; p++)
                ldmx4(bfr[p], Bbase + boff[p] + kk * 4u);
            #pragma unroll
            for (int mt = 0; mt < 4; mt++) {
                #pragma unroll
                for (int nt = 0; nt < 4; nt++)
                    mma_tf32(acc[mt][nt], afr[mt], &bfr[nt >> 1][(nt & 1) * 2]);
            }
        }
        __syncthreads();
    }

    // Epilogue
    #pragma unroll
    for (int mt = 0; mt < 4; mt++) {
        const int r0 = m0 + m_w + mt * 16 + g;
        #pragma unroll
        for (int nt = 0; nt < 4; nt++) {
            const int col = n0 + n_w + nt * 8 + tg * 2;
            const float b0 = bias[col], b1 = bias[col + 1];
            float v0 = acc[mt][nt][0] + b0;
            float v1 = acc[mt][nt][1] + b1;
            float v2 = acc[mt][nt][2] + b0;
            float v3 = acc[mt][nt][3] + b1;
            if (DO_GELU) {
                v0 = gelu_exact(v0); v1 = gelu_exact(v1);
                v2 = gelu_exact(v2); v3 = gelu_exact(v3);
            }
            *reinterpret_cast<float2*>(&C[(size_t)r0 * N + col])       = make_float2(v0, v1);
            *reinterpret_cast<float2*>(&C[(size_t)(r0 + 8) * N + col]) = make_float2(v2, v3);
        }
    }
}

// ---------------- elementwise tf32 RNA rounding ----------------
__global__ __launch_bounds__(256) void cvt_tf32_kernel(
    const float4* __restrict__ in, float4* __restrict__ out, int n4)
{
    int i = blockIdx.x * blockDim.x + threadIdx.x;
    if (i < n4) {
        float4 v = in[i];
        v.x = __uint_as_float(f2tf32(v.x));
        v.y = __uint_as_float(f2tf32(v.y));
        v.z = __uint_as_float(f2tf32(v.z));
        v.w = __uint_as_float(f2tf32(v.w));
        out[i] = v;
    }
}

// ---------------- 2D RoPE + merge transpose, fully coalesced ----------------
// One warp per output row m. Thread handles float4 dim-chunk j of each of the
// 4 source tokens, writes 64 B contiguous at column 16*j.
__global__ __launch_bounds__(256) void rope_merge(
    const float* __restrict__ pe,
    const float* __restrict__ cosx, const float* __restrict__ sinx,
    const float* __restrict__ cosy, const float* __restrict__ siny,
    float* __restrict__ A2)
{
    const int wid  = threadIdx.x >> 5;
    const int lane = threadIdx.x & 31;
    const int m = blockIdx.x * 8 + wid;          // 0..8191
    const int b = m >> 10;
    const int rem = m & 1023;
    const int Y = rem >> 5, X = rem & 31;
    const int y0 = 2 * Y, x0 = 2 * X;

    const float* rows[4];
    #pragma unroll
    for (int p = 0; p < 2; p++)
        #pragma unroll
        for (int q = 0; q < 2; q++)
            rows[p * 2 + q] = pe + ((size_t)(b * 4096 + (y0 + p) * 64 + (x0 + q))) * EMBED;

    float* dst = A2 + (size_t)m * K2;

    #pragma unroll
    for (int it = 0; it < 8; it++) {
        const int j = it * 32 + lane;            // float4 chunk 0..255 (dims 4j..4j+3)
        const bool h1 = (j >= 128);              // second half: y-rope
        const int i0 = h1 ? (2 * j - 256) : (2 * j);
        const float* ct = h1 ? cosy : cosx;
        const float* st = h1 ? siny : sinx;

        float o[4][4];                           // [pq][d]
        #pragma unroll
        for (int p = 0; p < 2; p++) {
            #pragma unroll
            for (int q = 0; q < 2; q++) {
                const int pos = h1 ? (y0 + p) : (x0 + q);
                const float c0 = ct[pos * 256 + i0],     s0 = st[pos * 256 + i0];
                const float c1 = ct[pos * 256 + i0 + 1], s1 = st[pos * 256 + i0 + 1];
                const float4 v = reinterpret_cast<const float4*>(rows[p * 2 + q])[j];
                const int pq = p * 2 + q;
                o[pq][0] = __uint_as_float(f2tf32(v.x * c0 - v.y * s0));
                o[pq][1] = __uint_as_float(f2tf32(v.x * s0 + v.y * c0));
                o[pq][2] = __uint_as_float(f2tf32(v.z * c1 - v.w * s1));
                o[pq][3] = __uint_as_float(f2tf32(v.z * s1 + v.w * c1));
            }
        }
        // dst column e*4 + pq, e = 4j+d  → contiguous 16 floats at 16j
        #pragma unroll
        for (int d = 0; d < 4; d++) {
            float4 w = make_float4(o[0][d], o[1][d], o[2][d], o[3][d]);
            reinterpret_cast<float4*>(dst)[4 * j + d] = w;
        }
    }
}

// ---------------- launch ----------------
extern "C" void kernel_launch(void* const* d_in, const int* in_sizes, int n_in,
                              void* d_out, int out_size)
{
    const float* px = (const float*)d_in[0];   // pixel_values [32768, 588]
    const float* pw = (const float*)d_in[2];   // patch_w [1024, 588]
    const float* pb = (const float*)d_in[3];   // patch_b [1024]
    const float* dw = (const float*)d_in[4];   // dense_w [2048, 4096]
    const float* db = (const float*)d_in[5];   // dense_b [2048]
    const float* cx = (const float*)d_in[6];
    const float* sx = (const float*)d_in[7];
    const float* cy = (const float*)d_in[8];
    const float* sy = (const float*)d_in[9];
    float* out = (float*)d_out;                // [8192, 2048]

    float *pe, *A2, *w1, *w2;
    cudaGetSymbolAddress((void**)&pe, g_pe);
    cudaGetSymbolAddress((void**)&A2, g_A2);
    cudaGetSymbolAddress((void**)&w1, g_w1);
    cudaGetSymbolAddress((void**)&w2, g_w2);

    const int SMEM = 2 * (BM + BN) * SJ * sizeof(float);  // 73728 bytes
    cudaFuncSetAttribute(mma_gemm_nt<1>, cudaFuncAttributeMaxDynamicSharedMemorySize, SMEM);
    cudaFuncSetAttribute(mma_gemm_nt<0>, cudaFuncAttributeMaxDynamicSharedMemorySize, SMEM);

    // Pre-round operands to tf32 (RNA). Pixels staged in g_A2 (overwritten by rope later).
    {
        int n4 = N_TOK * K1 / 4;
        cvt_tf32_kernel<<<(n4 + 255) / 256, 256>>>((const float4*)px, (float4*)A2, n4);
        n4 = EMBED * K1 / 4;
        cvt_tf32_kernel<<<(n4 + 255) / 256, 256>>>((const float4*)pw, (float4*)w1, n4);
        n4 = LLM * K2 / 4;
        cvt_tf32_kernel<<<(n4 + 255) / 256, 256>>>((const float4*)dw, (float4*)w2, n4);
    }

    // Stage 1: pe = gelu(px_tf32 @ pw_tf32^T + pb)
    {
        dim3 grid(EMBED / BN, N_TOK / BM);     // (8, 256)
        mma_gemm_nt<1><<<grid, 256, SMEM>>>(A2, w1, pb, pe, N_TOK, EMBED, K1);
    }

    // Stage 2: RoPE + merge transpose (tf32-rounded) into A2, coalesced
    rope_merge<<<M2 / 8, 256>>>(pe, cx, sx, cy, sy, A2);

    // Stage 3: out = A2 @ dw_tf32^T + db
    {
        dim3 grid(LLM / BN, M2 / BM);          // (16, 64)
        mma_gemm_nt<0><<<grid, 256, SMEM>>>(A2, w2, db, out, M2, LLM, K2);
    }
}

// round 12
// speedup vs baseline: 2.2200x; 1.8263x over previous
#include <cuda_runtime.h>
#include <cuda_fp16.h>
#include <math.h>
#include <cstdint>

// Problem constants (grid_hw fixed 64x64 for all 8 images)
#define N_TOK   32768
#define EMBED   1024
#define K1      588
#define K1P     592        // fp16 row stride, 16B-aligned, zero-padded
#define LLM     2048
#define M2      8192
#define K2      4096

// Scratch (device globals — no allocation allowed)
__device__ float  g_pe[(size_t)N_TOK * EMBED];     // gelu(patch GEMM), fp32
__device__ __half g_pxh[(size_t)N_TOK * K1P];      // fp16 pixels, padded rows
__device__ __half g_w1h[(size_t)EMBED * K1P];      // fp16 patch_w, padded rows
__device__ __half g_w2h[(size_t)LLM * K2];         // fp16 dense_w
__device__ __half g_A2h[(size_t)M2 * K2];          // fp16 rope'd merge-layout A2

// GEMM tiling: CTA 128x128, 8 warps of 64x32, K-chunk 64 halves, 2 CTAs/SM
#define BM 128
#define BN 128
#define BK 64
#define SJH 72    // smem row stride in halves (64+8): conflict-free ldmatrix & stores

__device__ __forceinline__ float gelu_exact(float x) {
    return 0.5f * x * (1.0f + erff(x * 0.70710678118654752f));
}
__device__ __forceinline__ void cp_async16(void* smem_dst, const void* gsrc, int src_bytes) {
    unsigned s = (unsigned)__cvta_generic_to_shared(smem_dst);
    asm volatile("cp.async.cg.shared.global [%0], [%1], 16, %2;\n" :: "r"(s), "l"(gsrc), "r"(src_bytes));
}
__device__ __forceinline__ void cp_commit() { asm volatile("cp.async.commit_group;\n"); }
__device__ __forceinline__ void cp_wait1()  { asm volatile("cp.async.wait_group 1;\n"); }

__device__ __forceinline__ void ldmx4(unsigned* r, unsigned saddr) {
    asm volatile("ldmatrix.sync.aligned.m8n8.x4.shared.b16 {%0,%1,%2,%3}, [%4];"
        : "=r"(r[0]), "=r"(r[1]), "=r"(r[2]), "=r"(r[3]) : "r"(saddr));
}
__device__ __forceinline__ void mma_f16(float* d, const unsigned* a, const unsigned* b) {
    asm volatile(
        "mma.sync.aligned.m16n8k16.row.col.f32.f16.f16.f32 "
        "{%0,%1,%2,%3}, {%4,%5,%6,%7}, {%8,%9}, {%0,%1,%2,%3};"
        : "+f"(d[0]), "+f"(d[1]), "+f"(d[2]), "+f"(d[3])
        : "r"(a[0]), "r"(a[1]), "r"(a[2]), "r"(a[3]), "r"(b[0]), "r"(b[1]));
}

// C[M,N] = A[M,K]*B[N,K]^T + bias (+GELU). A,B fp16 K-major (K = row stride, halves).
// M%128==0, N%128==0, K%8==0 (K-tail zero-filled via cp.async masking).
template<int DO_GELU>
__global__ __launch_bounds__(256, 2) void hgemm_nt(
    const __half* __restrict__ A, const __half* __restrict__ B,
    const float* __restrict__ bias, float* __restrict__ C,
    int M, int N, int K)
{
    extern __shared__ __half smem[];
    __half* As = smem;                       // [2][BM * SJH]
    __half* Bs = smem + 2 * BM * SJH;        // [2][BN * SJH]

    const int tid  = threadIdx.x;
    const int lane = tid & 31;
    const int wid  = tid >> 5;
    const int m_w  = (wid >> 2) * 64;        // warp row offset (0,64)
    const int n_w  = (wid & 3) * 32;         // warp col offset (0,32,64,96)
    const int g    = lane >> 2;              // 0..7
    const int tg   = lane & 3;               // 0..3

    const int m0 = blockIdx.y * BM;
    const int n0 = blockIdx.x * BN;

    const unsigned sm_u = (unsigned)__cvta_generic_to_shared(smem);
    const unsigned As_u = sm_u;
    const unsigned Bs_u = sm_u + 2u * BM * SJH * 2u;
    const int lr8   = lane & 7;
    const int lsel1 = (lane >> 3) & 1;
    const int lsel2 = (lane >> 4) & 1;
    unsigned aoff[4], boff[2];
    #pragma unroll
    for (int mt = 0; mt < 4; mt++)
        aoff[mt] = ((m_w + mt * 16 + lr8 + lsel1 * 8) * SJH + lsel2 * 8) * 2u;
    #pragma unroll
    for (int p = 0; p < 2; p++)
        boff[p]  = ((n_w + p * 16 + lr8 + lsel2 * 8) * SJH + lsel1 * 8) * 2u;

    float acc[4][4][4];
    #pragma unroll
    for (int i = 0; i < 4; i++)
        #pragma unroll
        for (int j = 0; j < 4; j++)
            #pragma unroll
            for (int r = 0; r < 4; r++) acc[i][j][r] = 0.0f;

    const int nKT = (K + BK - 1) / BK;

    auto issue = [&](int kt, int buf) {
        const int k0 = kt * BK;
        __half* Ab = As + buf * BM * SJH;
        __half* Bb = Bs + buf * BN * SJH;
        #pragma unroll
        for (int i = 0; i < 4; i++) {          // A: 128 rows * 8 chunks(8h) = 1024
            const int idx = tid + i * 256;
            const int r = idx >> 3, c = idx & 7;
            const int kc = k0 + c * 8;
            const int bytes = (kc < K) ? 16 : 0;
            const int ks = (kc < K) ? kc : 0;
            cp_async16(&Ab[r * SJH + c * 8], A + (size_t)(m0 + r) * K + ks, bytes);
        }
        #pragma unroll
        for (int i = 0; i < 4; i++) {          // B: 128 rows * 8 chunks = 1024
            const int idx = tid + i * 256;
            const int r = idx >> 3, c = idx & 7;
            const int kc = k0 + c * 8;
            const int bytes = (kc < K) ? 16 : 0;
            const int ks = (kc < K) ? kc : 0;
            cp_async16(&Bb[r * SJH + c * 8], B + (size_t)(n0 + r) * K + ks, bytes);
        }
    };

    issue(0, 0);
    cp_commit();

    for (int kt = 0; kt < nKT; kt++) {
        if (kt + 1 < nKT) issue(kt + 1, (kt + 1) & 1);
        cp_commit();
        cp_wait1();
        __syncthreads();

        const unsigned Abase = As_u + (unsigned)(kt & 1) * BM * SJH * 2u;
        const unsigned Bbase = Bs_u + (unsigned)(kt & 1) * BN * SJH * 2u;

        #pragma unroll
        for (int kk = 0; kk < BK; kk += 16) {
            unsigned afr[4][4];
            unsigned bfr[2][4];   // {b0(nt=2p), b1(nt=2p), b0(nt=2p+1), b1(nt=2p+1)}
            #pragma unroll
            for (int mt = 0; mt < 4; mt++)
                ldmx4(afr[mt], Abase + aoff[mt] + kk * 2u);
            #pragma unroll
            for (int p = 0; p < 2; p++)
                ldmx4(bfr[p], Bbase + boff[p] + kk * 2u);
            #pragma unroll
            for (int mt = 0; mt < 4; mt++) {
                #pragma unroll
                for (int nt = 0; nt < 4; nt++)
                    mma_f16(acc[mt][nt], afr[mt], &bfr[nt >> 1][(nt & 1) * 2]);
            }
        }
        __syncthreads();
    }

    // Epilogue
    #pragma unroll
    for (int mt = 0; mt < 4; mt++) {
        const int r0 = m0 + m_w + mt * 16 + g;
        #pragma unroll
        for (int nt = 0; nt < 4; nt++) {
            const int col = n0 + n_w + nt * 8 + tg * 2;
            const float b0 = bias[col], b1 = bias[col + 1];
            float v0 = acc[mt][nt][0] + b0;
            float v1 = acc[mt][nt][1] + b1;
            float v2 = acc[mt][nt][2] + b0;
            float v3 = acc[mt][nt][3] + b1;
            if (DO_GELU) {
                v0 = gelu_exact(v0); v1 = gelu_exact(v1);
                v2 = gelu_exact(v2); v3 = gelu_exact(v3);
            }
            *reinterpret_cast<float2*>(&C[(size_t)r0 * N + col])       = make_float2(v0, v1);
            *reinterpret_cast<float2*>(&C[(size_t)(r0 + 8) * N + col]) = make_float2(v2, v3);
        }
    }
}

// ---------------- fp32 -> fp16 conversion with optional row padding ----------------
// Each thread produces one 16B chunk (8 halves) of the padded output row.
__global__ __launch_bounds__(256) void cvt_f16_pad(
    const float* __restrict__ in, __half* __restrict__ out,
    int kin, int kout, int ncr, int total)
{
    const int idx = blockIdx.x * 256 + threadIdx.x;
    if (idx >= total) return;
    const int r = idx / ncr, c = idx % ncr;
    const float* src = in + (size_t)r * kin + c * 8;
    int valid = kin - c * 8; if (valid > 8) valid = 8;
    __half h[8];
    #pragma unroll
    for (int i = 0; i < 8; i++)
        h[i] = (i < valid) ? __float2half_rn(src[i]) : __ushort_as_half((unsigned short)0);
    *reinterpret_cast<uint4*>(out + (size_t)r * kout + c * 8) = *reinterpret_cast<const uint4*>(h);
}

// ---------------- 2D RoPE + merge transpose, fp16 output, fully coalesced ----------------
// One warp per output row m. Thread handles float4 dim-chunk j of each of the
// 4 source tokens, writes 32 B contiguous fp16 at column 16*j.
__global__ __launch_bounds__(256) void rope_merge(
    const float* __restrict__ pe,
    const float* __restrict__ cosx, const float* __restrict__ sinx,
    const float* __restrict__ cosy, const float* __restrict__ siny,
    __half* __restrict__ A2)
{
    const int wid  = threadIdx.x >> 5;
    const int lane = threadIdx.x & 31;
    const int m = blockIdx.x * 8 + wid;          // 0..8191
    const int b = m >> 10;
    const int rem = m & 1023;
    const int Y = rem >> 5, X = rem & 31;
    const int y0 = 2 * Y, x0 = 2 * X;

    const float* rows[4];
    #pragma unroll
    for (int p = 0; p < 2; p++)
        #pragma unroll
        for (int q = 0; q < 2; q++)
            rows[p * 2 + q] = pe + ((size_t)(b * 4096 + (y0 + p) * 64 + (x0 + q))) * EMBED;

    __half* dst = A2 + (size_t)m * K2;

    #pragma unroll
    for (int it = 0; it < 8; it++) {
        const int j = it * 32 + lane;            // float4 chunk 0..255 (dims 4j..4j+3)
        const bool h1 = (j >= 128);              // second half: y-rope
        const int i0 = h1 ? (2 * j - 256) : (2 * j);
        const float* ct = h1 ? cosy : cosx;
        const float* st = h1 ? siny : sinx;

        __half hv[16];                           // index d*4 + pq
        #pragma unroll
        for (int p = 0; p < 2; p++) {
            #pragma unroll
            for (int q = 0; q < 2; q++) {
                const int pos = h1 ? (y0 + p) : (x0 + q);
                const float c0 = ct[pos * 256 + i0],     s0 = st[pos * 256 + i0];
                const float c1 = ct[pos * 256 + i0 + 1], s1 = st[pos * 256 + i0 + 1];
                const float4 v = reinterpret_cast<const float4*>(rows[p * 2 + q])[j];
                const int pq = p * 2 + q;
                hv[0 * 4 + pq] = __float2half_rn(v.x * c0 - v.y * s0);
                hv[1 * 4 + pq] = __float2half_rn(v.x * s0 + v.y * c0);
                hv[2 * 4 + pq] = __float2half_rn(v.z * c1 - v.w * s1);
                hv[3 * 4 + pq] = __float2half_rn(v.z * s1 + v.w * c1);
            }
        }
        // dst column e*4 + pq, e = 4j+d  → contiguous 16 halves at 16j
        uint4* d16 = reinterpret_cast<uint4*>(dst + 16 * j);
        d16[0] = reinterpret_cast<const uint4*>(hv)[0];
        d16[1] = reinterpret_cast<const uint4*>(hv)[1];
    }
}

// ---------------- launch ----------------
extern "C" void kernel_launch(void* const* d_in, const int* in_sizes, int n_in,
                              void* d_out, int out_size)
{
    const float* px = (const float*)d_in[0];   // pixel_values [32768, 588]
    const float* pw = (const float*)d_in[2];   // patch_w [1024, 588]
    const float* pb = (const float*)d_in[3];   // patch_b [1024]
    const float* dw = (const float*)d_in[4];   // dense_w [2048, 4096]
    const float* db = (const float*)d_in[5];   // dense_b [2048]
    const float* cx = (const float*)d_in[6];
    const float* sx = (const float*)d_in[7];
    const float* cy = (const float*)d_in[8];
    const float* sy = (const float*)d_in[9];
    float* out = (float*)d_out;                // [8192, 2048]

    float* pe;
    __half *pxh, *w1h, *w2h, *A2h;
    cudaGetSymbolAddress((void**)&pe,  g_pe);
    cudaGetSymbolAddress((void**)&pxh, g_pxh);
    cudaGetSymbolAddress((void**)&w1h, g_w1h);
    cudaGetSymbolAddress((void**)&w2h, g_w2h);
    cudaGetSymbolAddress((void**)&A2h, g_A2h);

    const int SMEM = 2 * (BM + BN) * SJH * sizeof(__half);  // 73728 bytes
    cudaFuncSetAttribute(hgemm_nt<1>, cudaFuncAttributeMaxDynamicSharedMemorySize, SMEM);
    cudaFuncSetAttribute(hgemm_nt<0>, cudaFuncAttributeMaxDynamicSharedMemorySize, SMEM);

    // Convert operands to fp16 (pixel & patch_w rows padded 588 -> 592)
    {
        int total = N_TOK * (K1P / 8);
        cvt_f16_pad<<<(total + 255) / 256, 256>>>(px, pxh, K1, K1P, K1P / 8, total);
        total = EMBED * (K1P / 8);
        cvt_f16_pad<<<(total + 255) / 256, 256>>>(pw, w1h, K1, K1P, K1P / 8, total);
        total = LLM * (K2 / 8);
        cvt_f16_pad<<<(total + 255) / 256, 256>>>(dw, w2h, K2, K2, K2 / 8, total);
    }

    // Stage 1: pe = gelu(px_h @ pw_h^T + pb)
    {
        dim3 grid(EMBED / BN, N_TOK / BM);     // (8, 256)
        hgemm_nt<1><<<grid, 256, SMEM>>>(pxh, w1h, pb, pe, N_TOK, EMBED, K1P);
    }

    // Stage 2: RoPE + merge transpose (fp32 math, fp16 out) into A2h
    rope_merge<<<M2 / 8, 256>>>(pe, cx, sx, cy, sy, A2h);

    // Stage 3: out = A2_h @ dw_h^T + db
    {
        dim3 grid(LLM / BN, M2 / BM);          // (16, 64)
        hgemm_nt<0><<<grid, 256, SMEM>>>(A2h, w2h, db, out, M2, LLM, K2);
    }
}